// round 1
// baseline (speedup 1.0000x reference)
#include <cuda_runtime.h>
#include <cstddef>

#define BATCH 16
#define CIN 256
#define COUT 256
#define HH 64
#define WW 64
#define NEMB 8
#define TAPS 9
#define WPB (CIN * COUT * TAPS)   // 589824 floats per batch sample

// Scratch (allocation-free rule: __device__ globals)
__device__ float g_xmean[BATCH * CIN];
__device__ float g_mix[BATCH * NEMB];
__device__ float g_wmix[(size_t)BATCH * WPB];   // 37.75 MB mixed per-sample weights

// ---------------------------------------------------------------------------
// Kernel 1: per-(b,c) spatial mean of x.  4096 blocks x 256 threads.
// ---------------------------------------------------------------------------
__global__ void k_colmean(const float* __restrict__ x) {
    int bc = blockIdx.x;                       // b*256 + c
    const float* p = x + (size_t)bc * (HH * WW);
    float s = 0.f;
    for (int i = threadIdx.x; i < HH * WW; i += 256) s += p[i];
    __shared__ float sm[256];
    sm[threadIdx.x] = s;
    __syncthreads();
    for (int st = 128; st > 0; st >>= 1) {
        if (threadIdx.x < st) sm[threadIdx.x] += sm[threadIdx.x + st];
        __syncthreads();
    }
    if (threadIdx.x == 0) g_xmean[bc] = sm[0] * (1.f / (HH * WW));
}

// ---------------------------------------------------------------------------
// Kernel 2: pooled = xmean @ Wc^T + bc ; logits = pooled @ Wd^T + bd ; softmax.
// Single block, 256 threads. Tiny.
// ---------------------------------------------------------------------------
__global__ void k_mix(const float* __restrict__ convw, const float* __restrict__ convb,
                      const float* __restrict__ dw, const float* __restrict__ db) {
    __shared__ float pooled[BATCH][CIN];
    __shared__ float logits[BATCH][NEMB];
    int d = threadIdx.x;                       // 0..255
    for (int b = 0; b < BATCH; b++) {
        float acc = convb[d];
        const float* xm = &g_xmean[b * CIN];
        const float* wr = &convw[d * CIN];
        #pragma unroll 8
        for (int c = 0; c < CIN; c++) acc += xm[c] * wr[c];
        pooled[b][d] = acc;
    }
    __syncthreads();
    if (threadIdx.x < BATCH * NEMB) {
        int b = threadIdx.x / NEMB, e = threadIdx.x % NEMB;
        float acc = db[e];
        #pragma unroll 8
        for (int dd = 0; dd < CIN; dd++) acc += pooled[b][dd] * dw[e * CIN + dd];
        logits[b][e] = acc;
    }
    __syncthreads();
    if (threadIdx.x < BATCH) {
        int b = threadIdx.x;
        float mx = -1e30f;
        #pragma unroll
        for (int e = 0; e < NEMB; e++) mx = fmaxf(mx, logits[b][e]);
        float ex[NEMB], s = 0.f;
        #pragma unroll
        for (int e = 0; e < NEMB; e++) { ex[e] = expf(logits[b][e] - mx); s += ex[e]; }
        float inv = 1.f / s;
        #pragma unroll
        for (int e = 0; e < NEMB; e++) g_mix[b * NEMB + e] = ex[e] * inv;
    }
}

// ---------------------------------------------------------------------------
// Kernel 3: g_wmix[b, j] = sum_e mix[b,e] * KE[e, j]   (j over 589824, float4)
// KE (18.9MB) fits in L2 -> read DRAM once even though touched per-b.
// ---------------------------------------------------------------------------
__global__ void k_wmix(const float* __restrict__ ke) {
    __shared__ float mix[BATCH * NEMB];
    if (threadIdx.x < BATCH * NEMB) mix[threadIdx.x] = g_mix[threadIdx.x];
    __syncthreads();
    int j = blockIdx.x * blockDim.x + threadIdx.x;   // float4 index, < WPB/4
    const float4* ke4 = (const float4*)ke;
    float4 kv[NEMB];
    #pragma unroll
    for (int e = 0; e < NEMB; e++) kv[e] = ke4[(size_t)e * (WPB / 4) + j];
    float4* w4 = (float4*)g_wmix;
    for (int b = 0; b < BATCH; b++) {
        float4 acc = make_float4(0.f, 0.f, 0.f, 0.f);
        #pragma unroll
        for (int e = 0; e < NEMB; e++) {
            float m = mix[b * NEMB + e];
            acc.x += m * kv[e].x; acc.y += m * kv[e].y;
            acc.z += m * kv[e].z; acc.w += m * kv[e].w;
        }
        w4[(size_t)b * (WPB / 4) + j] = acc;
    }
}

// ---------------------------------------------------------------------------
// Kernel 4: per-sample 3x3 conv, implicit-GEMM style, fp32.
// Block: 64 o x (4 rows x 64 cols) = 64x256 outputs, 256 threads,
// each thread 8 o x 8 px. Inner tap: 8 broadcast w-LDS + 8 stride-1 x-LDS
// per 64 FMA -> FMA-limited.
// ---------------------------------------------------------------------------
#define OTILE 64
#define RTILE 4
#define ICT 8

__global__ void __launch_bounds__(256) k_conv(const float* __restrict__ x,
                                              float* __restrict__ out) {
    int b = blockIdx.z;
    int o_base = blockIdx.y * OTILE;
    int y_base = blockIdx.x * RTILE;
    int tid = threadIdx.x;
    int tx = tid & 31;       // column group (stride-32 cols)
    int ty = tid >> 5;       // o group (8 o's each)

    __shared__ float ws[OTILE][ICT * TAPS];          // [o][ic*9+tap]   18432 B
    __shared__ float xs[ICT][RTILE + 2][WW + 2];     // rows y-1..y+4   12672 B

    float acc[8][8];
    #pragma unroll
    for (int a = 0; a < 8; a++)
        #pragma unroll
        for (int p = 0; p < 8; p++) acc[a][p] = 0.f;

    const float* wsrc0 = g_wmix + (size_t)b * WPB + (size_t)o_base * (CIN * TAPS);
    const float* xsrc0 = x + (size_t)b * CIN * HH * WW;

    for (int i_base = 0; i_base < CIN; i_base += ICT) {
        // --- load weights: 64 o x (8 ic x 9 taps) = 4608 floats ---
        const float* wsrc = wsrc0 + (size_t)i_base * TAPS;
        #pragma unroll
        for (int t = tid; t < OTILE * ICT * TAPS; t += 256) {
            int o = t / (ICT * TAPS);
            int r = t - o * (ICT * TAPS);            // ic*9 + tap (contiguous in src)
            ws[o][r] = wsrc[(size_t)o * (CIN * TAPS) + r];
        }
        // --- load x tile: 8 ic x 6 rows x 66 cols (zero-padded halo) ---
        for (int t = tid; t < ICT * 6 * (WW + 2); t += 256) {
            int ic = t / (6 * (WW + 2));
            int rem = t - ic * (6 * (WW + 2));
            int rr = rem / (WW + 2);
            int c = rem - rr * (WW + 2);
            int y = y_base + rr - 1;
            int col = c - 1;
            float v = 0.f;
            if ((unsigned)y < HH && (unsigned)col < WW)
                v = xsrc0[((size_t)(i_base + ic)) * (HH * WW) + y * WW + col];
            xs[ic][rr][c] = v;
        }
        __syncthreads();

        #pragma unroll
        for (int ic = 0; ic < ICT; ic++) {
            #pragma unroll
            for (int k1 = 0; k1 < 3; k1++) {
                #pragma unroll
                for (int k2 = 0; k2 < 3; k2++) {
                    float wv[8];
                    #pragma unroll
                    for (int oo = 0; oo < 8; oo++)
                        wv[oo] = ws[ty * 8 + oo][ic * 9 + k1 * 3 + k2];
                    float xv[8];
                    #pragma unroll
                    for (int ry = 0; ry < 4; ry++)
                        #pragma unroll
                        for (int jj = 0; jj < 2; jj++)
                            xv[ry * 2 + jj] = xs[ic][ry + k1][tx + 32 * jj + k2];
                    #pragma unroll
                    for (int oo = 0; oo < 8; oo++)
                        #pragma unroll
                        for (int p = 0; p < 8; p++)
                            acc[oo][p] += wv[oo] * xv[p];
                }
            }
        }
        __syncthreads();
    }

    // --- write 8 o x 4 rows x 2 col-groups, coalesced across tx ---
    #pragma unroll
    for (int oo = 0; oo < 8; oo++) {
        int o = o_base + ty * 8 + oo;
        #pragma unroll
        for (int ry = 0; ry < 4; ry++) {
            int y = y_base + ry;
            float* op = out + ((size_t)(b * COUT + o)) * (HH * WW) + y * WW;
            op[tx]      = acc[oo][ry * 2 + 0];
            op[tx + 32] = acc[oo][ry * 2 + 1];
        }
    }
}

// ---------------------------------------------------------------------------
extern "C" void kernel_launch(void* const* d_in, const int* in_sizes, int n_in,
                              void* d_out, int out_size) {
    const float* x     = (const float*)d_in[0];   // (16,256,64,64)
    const float* ke    = (const float*)d_in[1];   // (8,256,256,3,3)
    const float* convw = (const float*)d_in[2];   // (256,256)
    const float* convb = (const float*)d_in[3];   // (256,)
    const float* dw    = (const float*)d_in[4];   // (8,256)
    const float* db    = (const float*)d_in[5];   // (8,)
    float* out = (float*)d_out;                   // (16,256,64,64)

    k_colmean<<<BATCH * CIN, 256>>>(x);
    k_mix<<<1, 256>>>(convw, convb, dw, db);
    k_wmix<<<WPB / 4 / 256, 256>>>(ke);
    dim3 g(HH / RTILE, COUT / OTILE, BATCH);      // (16, 4, 16)
    k_conv<<<g, 256>>>(x, out);
}